// round 16
// baseline (speedup 1.0000x reference)
#include <cuda_runtime.h>
#include <cuda_bf16.h>
#include <cstdint>

// ---------------------------------------------------------------------------
// SAGEMean3: out = relu( [x | mean_in | mean_out] @ W + b )
// Bucketed-adjacency gather aggregation + bf16x3 mma.sync GEMM
// (persistent 128x128 tiles, 256 threads, GBK=32, cp.async.ca, 2-stage,
//  2 CTAs/SM, grid=296). Single default stream (harness contract).
// 4 kernels: setup, fill, gather, gemm.
// ---------------------------------------------------------------------------

#define IN_DIM    128
#define K_DIM     384
#define OUT_DIM   1024
#define N_MAX     50000
#define M_PAD     50048          // multiple of 128
#define CAP       96             // degrees ~Poisson(12): P(>96) ~ 1e-50

__device__ __align__(16) __nv_bfloat16 g_Ahi[(size_t)M_PAD * K_DIM];
__device__ __align__(16) __nv_bfloat16 g_Alo[(size_t)M_PAD * K_DIM];
__device__ __align__(16) __nv_bfloat16 g_Bhi[(size_t)K_DIM * OUT_DIM];
__device__ __align__(16) __nv_bfloat16 g_Blo[(size_t)K_DIM * OUT_DIM];
__device__ int g_cnt[2 * N_MAX];
__device__ int g_adjb[(size_t)2 * N_MAX * CAP];
__device__ int g_idx64;

// ---------------------------------------------------------------------------
__device__ __forceinline__ void split4(const float vv[4],
                                       __nv_bfloat16 h[4], __nv_bfloat16 l[4])
{
    #pragma unroll
    for (int e = 0; e < 4; e++) {
        h[e] = __float2bfloat16(vv[e]);
        l[e] = __float2bfloat16(vv[e] - __bfloat162float(h[e]));
    }
}

// ---------------------------------------------------------------------------
// K1: setup — detect dtype, zero counters, zero GEMM pad rows, convert W.
// ---------------------------------------------------------------------------
__global__ void setup_kernel(const long long* __restrict__ ei,
                             const float* __restrict__ W, int n, int E)
{
    if (blockIdx.x == 0) {
        __shared__ int ok;
        if (threadIdx.x == 0) ok = 1;
        __syncthreads();
        int lim = 2 * E < 2048 ? 2 * E : 2048;
        for (int i = threadIdx.x; i < lim; i += blockDim.x) {
            long long v = ei[i];
            if (v < 0 || v >= n) ok = 0;
        }
        __syncthreads();
        if (threadIdx.x == 0) g_idx64 = ok;
    }

    const size_t tid = (size_t)blockIdx.x * blockDim.x + threadIdx.x;
    const size_t stride = (size_t)gridDim.x * blockDim.x;

    for (size_t i = tid; i < (size_t)(2 * n); i += stride) g_cnt[i] = 0;

    const size_t padv = (size_t)(M_PAD - N_MAX) * K_DIM / 8;
    for (size_t i = tid; i < padv; i += stride) {
        uint4 z = make_uint4(0, 0, 0, 0);
        *(uint4*)&g_Ahi[(size_t)N_MAX * K_DIM + i * 8] = z;
        *(uint4*)&g_Alo[(size_t)N_MAX * K_DIM + i * 8] = z;
    }

    const size_t wtot = (size_t)K_DIM * OUT_DIM / 4;
    for (size_t i = tid; i < wtot; i += stride) {
        float4 v = *(const float4*)&W[i * 4];
        float vv[4] = {v.x, v.y, v.z, v.w};
        __nv_bfloat16 h[4], l[4];
        split4(vv, h, l);
        *(uint2*)&g_Bhi[i * 4] = *(uint2*)h;
        *(uint2*)&g_Blo[i * 4] = *(uint2*)l;
    }
}

// ---------------------------------------------------------------------------
// edge decode (packed layout => dst at +E elements of detected dtype)
// ---------------------------------------------------------------------------
__device__ __forceinline__ void load_edge(const void* src_buf, const void* dst_buf,
                                          int e, int E, long long& s, long long& d)
{
    if (g_idx64) {
        const long long* sp = (const long long*)src_buf;
        const long long* dp = dst_buf ? (const long long*)dst_buf : sp + E;
        s = sp[e]; d = dp[e];
    } else {
        const int* sp = (const int*)src_buf;
        const int* dp = dst_buf ? (const int*)dst_buf : sp + E;
        s = sp[e]; d = dp[e];
    }
}

// ---------------------------------------------------------------------------
// K2: fill bucket adjacency (no histogram, no scan).
// ---------------------------------------------------------------------------
__global__ void fill_kernel(const void* __restrict__ src_buf,
                            const void* __restrict__ dst_buf, int n, int E)
{
    int e = blockIdx.x * blockDim.x + threadIdx.x;
    if (e >= E) return;
    long long s, d;
    load_edge(src_buf, dst_buf, e, E, s, d);
    if ((unsigned long long)s >= (unsigned long long)n ||
        (unsigned long long)d >= (unsigned long long)n) return;

    int p0 = atomicAdd(&g_cnt[(int)d], 1);
    int p1 = atomicAdd(&g_cnt[n + (int)s], 1);
    if (p0 < CAP) g_adjb[(size_t)d * CAP + p0] = (int)s;
    if (p1 < CAP) g_adjb[((size_t)n + (size_t)s) * CAP + p1] = (int)d;
}

// ---------------------------------------------------------------------------
// K3: gather means + convert x rows. One warp per (node, direction).
// ---------------------------------------------------------------------------
__device__ __forceinline__ void split_store(size_t ofs, const float vv[4])
{
    __nv_bfloat16 h[4], l[4];
    split4(vv, h, l);
    *(uint2*)&g_Ahi[ofs] = *(uint2*)h;
    *(uint2*)&g_Alo[ofs] = *(uint2*)l;
}

__global__ void gather_kernel(const float* __restrict__ x, int n)
{
    int seg  = (int)(((size_t)blockIdx.x * blockDim.x + threadIdx.x) >> 5);
    int lane = threadIdx.x & 31;
    if (seg >= 2 * n) return;

    int cnt = g_cnt[seg];
    if (cnt > CAP) cnt = CAP;
    const size_t base = (size_t)seg * CAP;
    int node = (seg < n) ? seg : seg - n;

    float4 acc = make_float4(0.f, 0.f, 0.f, 0.f);
    for (int b0 = 0; b0 < cnt; b0 += 32) {
        int m = cnt - b0;
        int idx = (b0 + lane < cnt) ? g_adjb[base + b0 + lane] : 0;
        if (m >= 32) {
            #pragma unroll
            for (int j = 0; j < 32; j++) {
                int nb = __shfl_sync(0xffffffffu, idx, j);
                float4 v = *(const float4*)&x[(size_t)nb * IN_DIM + lane * 4];
                acc.x += v.x; acc.y += v.y; acc.z += v.z; acc.w += v.w;
            }
        } else {
            for (int j = 0; j < m; j++) {
                int nb = __shfl_sync(0xffffffffu, idx, j);
                float4 v = *(const float4*)&x[(size_t)nb * IN_DIM + lane * 4];
                acc.x += v.x; acc.y += v.y; acc.z += v.z; acc.w += v.w;
            }
        }
    }

    float inv = 1.0f / fmaxf((float)cnt, 1.0f);
    float vv[4] = {acc.x * inv, acc.y * inv, acc.z * inv, acc.w * inv};
    int col = ((seg < n) ? 128 : 256) + lane * 4;
    split_store((size_t)node * K_DIM + col, vv);

    if (seg < n) {   // also convert this node's x row (cols 0..127)
        float4 v = *(const float4*)&x[(size_t)node * IN_DIM + lane * 4];
        float xv[4] = {v.x, v.y, v.z, v.w};
        split_store((size_t)node * K_DIM + lane * 4, xv);
    }
}

// ---------------------------------------------------------------------------
// K4: persistent bf16x3 GEMM. 128x128 tiles, 256 threads (8 warps, 4x2),
// warp tile 32x64, GBK=32, cp.async.ca, 2-stage, 2 CTAs/SM, grid=296.
// Grid-stride tile loop; stride 296 = 37*8 keeps each CTA on one B strip.
// ---------------------------------------------------------------------------
#define GBM 128
#define GBN 128
#define GBK 32
#define A_STRIDE 40      // 32 + 8 pad (bf16)
#define B_STRIDE 136     // 128 + 8 pad (bf16)
#define NCOL_TILES (OUT_DIM / GBN)          // 8
#define NROW_TILES (M_PAD / GBM)            // 391
#define NTILES (NCOL_TILES * NROW_TILES)    // 3128
#define GEMM_GRID 296                       // 148 SMs * 2 CTAs

#define AH_OFF(st) ((st) * GBM * A_STRIDE)
#define AL_OFF(st) (2 * GBM * A_STRIDE + (st) * GBM * A_STRIDE)
#define BH_OFF(st) (4 * GBM * A_STRIDE + (st) * GBK * B_STRIDE)
#define BL_OFF(st) (4 * GBM * A_STRIDE + 2 * GBK * B_STRIDE + (st) * GBK * B_STRIDE)
#define SMEM_BF16_TOTAL (4 * GBM * A_STRIDE + 4 * GBK * B_STRIDE)   // 37888 bf16 = 75776 B

__device__ __forceinline__ uint32_t smem_u32(const void* p)
{
    return (uint32_t)__cvta_generic_to_shared(p);
}

__device__ __forceinline__ void cp16(uint32_t saddr, const void* g)
{
    asm volatile("cp.async.ca.shared.global [%0], [%1], 16;" :: "r"(saddr), "l"(g));
}

__device__ __forceinline__ void ldsm_x4(uint32_t& r0, uint32_t& r1,
                                        uint32_t& r2, uint32_t& r3, uint32_t addr)
{
    asm volatile("ldmatrix.sync.aligned.m8n8.x4.shared.b16 {%0,%1,%2,%3}, [%4];"
                 : "=r"(r0), "=r"(r1), "=r"(r2), "=r"(r3) : "r"(addr));
}

__device__ __forceinline__ void ldsm_x4_t(uint32_t& r0, uint32_t& r1,
                                          uint32_t& r2, uint32_t& r3, uint32_t addr)
{
    asm volatile("ldmatrix.sync.aligned.m8n8.x4.trans.shared.b16 {%0,%1,%2,%3}, [%4];"
                 : "=r"(r0), "=r"(r1), "=r"(r2), "=r"(r3) : "r"(addr));
}

__device__ __forceinline__ void mma_bf16(float c[4], const uint32_t a[4],
                                         const uint32_t b[2])
{
    asm volatile(
        "mma.sync.aligned.m16n8k16.row.col.f32.bf16.bf16.f32 "
        "{%0,%1,%2,%3}, {%4,%5,%6,%7}, {%8,%9}, {%0,%1,%2,%3};"
        : "+f"(c[0]), "+f"(c[1]), "+f"(c[2]), "+f"(c[3])
        : "r"(a[0]), "r"(a[1]), "r"(a[2]), "r"(a[3]), "r"(b[0]), "r"(b[1]));
}

__global__ __launch_bounds__(256, 2)
void gemm_kernel(const float* __restrict__ bias, float* __restrict__ out, int M)
{
    extern __shared__ __nv_bfloat16 smem[];
    const uint32_t sbase = smem_u32(smem);

    const int tid  = threadIdx.x;
    const int warp = tid >> 5;
    const int lane = tid & 31;
    const int wm = (warp >> 1) * 32;
    const int wn = (warp & 1) * 64;

    const int a_row  = lane & 15;
    const int a_koff = (lane >> 4) * 8;
    const int b_k    = lane & 15;
    const int b_noff = (lane >> 4) * 8;
    const int g = lane >> 2;
    const int t = lane & 3;

    for (int tile = blockIdx.x; tile < NTILES; tile += GEMM_GRID) {
        const int rowBase = (tile >> 3) * GBM;
        const int colBase = (tile & 7) * GBN;

        float acc[2][8][4];
        #pragma unroll
        for (int i = 0; i < 2; i++)
            #pragma unroll
            for (int j = 0; j < 8; j++)
                #pragma unroll
                for (int c = 0; c < 4; c++) acc[i][j][c] = 0.f;

        auto load_stage = [&](int st, int k0) {
            #pragma unroll
            for (int it = 0; it < 2; it++) {
                int c = tid + it * 256;          // 0..511
                {   // A: 128 rows x 4 chunks of 16B
                    int r = c >> 2, o = (c & 3) * 8;
                    size_t gofs = (size_t)(rowBase + r) * K_DIM + k0 + o;
                    cp16(sbase + (AH_OFF(st) + r * A_STRIDE + o) * 2, &g_Ahi[gofs]);
                    cp16(sbase + (AL_OFF(st) + r * A_STRIDE + o) * 2, &g_Alo[gofs]);
                }
                {   // B: 32 rows x 16 chunks of 16B
                    int r = c >> 4, o = (c & 15) * 8;
                    size_t gofs = (size_t)(k0 + r) * OUT_DIM + colBase + o;
                    cp16(sbase + (BH_OFF(st) + r * B_STRIDE + o) * 2, &g_Bhi[gofs]);
                    cp16(sbase + (BL_OFF(st) + r * B_STRIDE + o) * 2, &g_Blo[gofs]);
                }
            }
            asm volatile("cp.async.commit_group;");
        };

        load_stage(0, 0);

        const int NITER = K_DIM / GBK;           // 12
        for (int itr = 0; itr < NITER; itr++) {
            if (itr + 1 < NITER) {
                load_stage((itr + 1) & 1, (itr + 1) * GBK);
                asm volatile("cp.async.wait_group 1;");
            } else {
                asm volatile("cp.async.wait_group 0;");
            }
            __syncthreads();

            const int st = itr & 1;
            const __nv_bfloat16* Ah = smem + AH_OFF(st);
            const __nv_bfloat16* Al = smem + AL_OFF(st);
            const __nv_bfloat16* Bh = smem + BH_OFF(st);
            const __nv_bfloat16* Bl = smem + BL_OFF(st);

            #pragma unroll
            for (int kk = 0; kk < GBK; kk += 16) {
                uint32_t ah[2][4], al[2][4];
                #pragma unroll
                for (int mi = 0; mi < 2; mi++) {
                    int row = wm + mi * 16 + a_row;
                    ldsm_x4(ah[mi][0], ah[mi][1], ah[mi][2], ah[mi][3],
                            smem_u32(Ah + row * A_STRIDE + kk + a_koff));
                    ldsm_x4(al[mi][0], al[mi][1], al[mi][2], al[mi][3],
                            smem_u32(Al + row * A_STRIDE + kk + a_koff));
                }
                uint32_t bh[8][2], bl[8][2];
                #pragma unroll
                for (int nj = 0; nj < 4; nj++) {
                    uint32_t r0, r1, r2, r3;
                    ldsm_x4_t(r0, r1, r2, r3,
                              smem_u32(Bh + (kk + b_k) * B_STRIDE + wn + nj * 16 + b_noff));
                    bh[nj*2][0] = r0; bh[nj*2][1] = r1;
                    bh[nj*2+1][0] = r2; bh[nj*2+1][1] = r3;
                    ldsm_x4_t(r0, r1, r2, r3,
                              smem_u32(Bl + (kk + b_k) * B_STRIDE + wn + nj * 16 + b_noff));
                    bl[nj*2][0] = r0; bl[nj*2][1] = r1;
                    bl[nj*2+1][0] = r2; bl[nj*2+1][1] = r3;
                }
                #pragma unroll
                for (int mi = 0; mi < 2; mi++)
                    #pragma unroll
                    for (int nj = 0; nj < 8; nj++) {
                        mma_bf16(acc[mi][nj], ah[mi], bh[nj]);
                        mma_bf16(acc[mi][nj], ah[mi], bl[nj]);
                        mma_bf16(acc[mi][nj], al[mi], bh[nj]);
                    }
            }
            __syncthreads();
        }

        // epilogue
        #pragma unroll
        for (int mi = 0; mi < 2; mi++) {
            int r0 = rowBase + wm + mi * 16 + g;
            int r1 = r0 + 8;
            #pragma unroll
            for (int nj = 0; nj < 8; nj++) {
                int c = colBase + wn + nj * 8 + t * 2;
                float2 bv = *(const float2*)&bias[c];
                if (r0 < M) {
                    float2 o;
                    o.x = fmaxf(acc[mi][nj][0] + bv.x, 0.f);
                    o.y = fmaxf(acc[mi][nj][1] + bv.y, 0.f);
                    *(float2*)&out[(size_t)r0 * OUT_DIM + c] = o;
                }
                if (r1 < M) {
                    float2 o;
                    o.x = fmaxf(acc[mi][nj][2] + bv.x, 0.f);
                    o.y = fmaxf(acc[mi][nj][3] + bv.y, 0.f);
                    *(float2*)&out[(size_t)r1 * OUT_DIM + c] = o;
                }
            }
        }
    }
}

// ---------------------------------------------------------------------------
// launch — 4 kernels on the default stream: setup, fill, gather, gemm
// ---------------------------------------------------------------------------
extern "C" void kernel_launch(void* const* d_in, const int* in_sizes, int n_in,
                              void* d_out, int out_size)
{
    const float* x = (const float*)d_in[0];
    const int n = in_sizes[0] / IN_DIM;
    float* out = (float*)d_out;

    const float* W;
    const float* b;
    const void* src_buf;
    const void* dst_buf;
    int E;

    if (n_in >= 5) {
        E = in_sizes[1];
        src_buf = d_in[1];
        dst_buf = d_in[2];
        W = (const float*)d_in[3];
        b = (const float*)d_in[4];
    } else {
        E = in_sizes[1] / 2;
        src_buf = d_in[1];
        dst_buf = nullptr;
        W = (const float*)d_in[2];
        b = (const float*)d_in[3];
    }

    setup_kernel<<<512, 256>>>((const long long*)d_in[1], W, n, E);
    fill_kernel<<<(E + 255) / 256, 256>>>(src_buf, dst_buf, n, E);
    {
        long long threads = (long long)(2 * n) * 32;
        gather_kernel<<<(int)((threads + 255) / 256), 256>>>(x, n);
    }
    {
        static const int smem_bytes = SMEM_BF16_TOTAL * 2;   // 75776
        cudaFuncSetAttribute(gemm_kernel,
                             cudaFuncAttributeMaxDynamicSharedMemorySize, smem_bytes);
        gemm_kernel<<<GEMM_GRID, 256, smem_bytes>>>(b, out, n);
    }
}

// round 17
// speedup vs baseline: 1.3863x; 1.3863x over previous
#include <cuda_runtime.h>
#include <cuda_fp16.h>
#include <cstdint>

// ---------------------------------------------------------------------------
// SAGEMean3: out = relu( [x | mean_in | mean_out] @ W + b )
// Bucketed-adjacency gather aggregation + fp16 asymmetric-split mma GEMM:
//   A = Ah + Al (fp16 Dekker split, exact to ~2^-23), B = fp16 single.
//   D = Ah@Bh + Al@Bh   (2 mmas per fragment pair; B rounding ~2^-12 rel)
// Mainloop = R12-proven: 128x128, GBK=32, cp.async.ca, 2-stage, 2 CTAs/SM.
// 4 kernels on the default stream: setup, fill, gather, gemm.
// ---------------------------------------------------------------------------

#define IN_DIM    128
#define K_DIM     384
#define OUT_DIM   1024
#define N_MAX     50000
#define M_PAD     50048          // multiple of 128
#define CAP       96             // degrees ~Poisson(12): P(>96) ~ 1e-50

__device__ __align__(16) __half g_Ahi[(size_t)M_PAD * K_DIM];
__device__ __align__(16) __half g_Alo[(size_t)M_PAD * K_DIM];
__device__ __align__(16) __half g_Bh[(size_t)K_DIM * OUT_DIM];
__device__ int g_cnt[2 * N_MAX];
__device__ int g_adjb[(size_t)2 * N_MAX * CAP];
__device__ int g_idx64;

// ---------------------------------------------------------------------------
__device__ __forceinline__ void split4h(const float vv[4],
                                        __half h[4], __half l[4])
{
    #pragma unroll
    for (int e = 0; e < 4; e++) {
        h[e] = __float2half_rn(vv[e]);
        l[e] = __float2half_rn(vv[e] - __half2float(h[e]));
    }
}

// ---------------------------------------------------------------------------
// K1: setup — detect dtype, zero counters, zero GEMM pad rows, convert W.
// ---------------------------------------------------------------------------
__global__ void setup_kernel(const long long* __restrict__ ei,
                             const float* __restrict__ W, int n, int E)
{
    if (blockIdx.x == 0) {
        __shared__ int ok;
        if (threadIdx.x == 0) ok = 1;
        __syncthreads();
        int lim = 2 * E < 2048 ? 2 * E : 2048;
        for (int i = threadIdx.x; i < lim; i += blockDim.x) {
            long long v = ei[i];
            if (v < 0 || v >= n) ok = 0;
        }
        __syncthreads();
        if (threadIdx.x == 0) g_idx64 = ok;
    }

    const size_t tid = (size_t)blockIdx.x * blockDim.x + threadIdx.x;
    const size_t stride = (size_t)gridDim.x * blockDim.x;

    for (size_t i = tid; i < (size_t)(2 * n); i += stride) g_cnt[i] = 0;

    const size_t padv = (size_t)(M_PAD - N_MAX) * K_DIM / 8;
    for (size_t i = tid; i < padv; i += stride) {
        uint4 z = make_uint4(0, 0, 0, 0);
        *(uint4*)&g_Ahi[(size_t)N_MAX * K_DIM + i * 8] = z;
        *(uint4*)&g_Alo[(size_t)N_MAX * K_DIM + i * 8] = z;
    }

    // W -> single fp16
    const size_t wtot = (size_t)K_DIM * OUT_DIM / 4;
    for (size_t i = tid; i < wtot; i += stride) {
        float4 v = *(const float4*)&W[i * 4];
        __half h[4];
        h[0] = __float2half_rn(v.x);
        h[1] = __float2half_rn(v.y);
        h[2] = __float2half_rn(v.z);
        h[3] = __float2half_rn(v.w);
        *(uint2*)&g_Bh[i * 4] = *(uint2*)h;
    }
}

// ---------------------------------------------------------------------------
// edge decode (packed layout => dst at +E elements of detected dtype)
// ---------------------------------------------------------------------------
__device__ __forceinline__ void load_edge(const void* src_buf, const void* dst_buf,
                                          int e, int E, long long& s, long long& d)
{
    if (g_idx64) {
        const long long* sp = (const long long*)src_buf;
        const long long* dp = dst_buf ? (const long long*)dst_buf : sp + E;
        s = sp[e]; d = dp[e];
    } else {
        const int* sp = (const int*)src_buf;
        const int* dp = dst_buf ? (const int*)dst_buf : sp + E;
        s = sp[e]; d = dp[e];
    }
}

// ---------------------------------------------------------------------------
// K2: fill bucket adjacency (no histogram, no scan).
// ---------------------------------------------------------------------------
__global__ void fill_kernel(const void* __restrict__ src_buf,
                            const void* __restrict__ dst_buf, int n, int E)
{
    int e = blockIdx.x * blockDim.x + threadIdx.x;
    if (e >= E) return;
    long long s, d;
    load_edge(src_buf, dst_buf, e, E, s, d);
    if ((unsigned long long)s >= (unsigned long long)n ||
        (unsigned long long)d >= (unsigned long long)n) return;

    int p0 = atomicAdd(&g_cnt[(int)d], 1);
    int p1 = atomicAdd(&g_cnt[n + (int)s], 1);
    if (p0 < CAP) g_adjb[(size_t)d * CAP + p0] = (int)s;
    if (p1 < CAP) g_adjb[((size_t)n + (size_t)s) * CAP + p1] = (int)d;
}

// ---------------------------------------------------------------------------
// K3: gather means + convert x rows. One warp per (node, direction).
// ---------------------------------------------------------------------------
__device__ __forceinline__ void split_store(size_t ofs, const float vv[4])
{
    __half h[4], l[4];
    split4h(vv, h, l);
    *(uint2*)&g_Ahi[ofs] = *(uint2*)h;
    *(uint2*)&g_Alo[ofs] = *(uint2*)l;
}

__global__ void gather_kernel(const float* __restrict__ x, int n)
{
    int seg  = (int)(((size_t)blockIdx.x * blockDim.x + threadIdx.x) >> 5);
    int lane = threadIdx.x & 31;
    if (seg >= 2 * n) return;

    int cnt = g_cnt[seg];
    if (cnt > CAP) cnt = CAP;
    const size_t base = (size_t)seg * CAP;
    int node = (seg < n) ? seg : seg - n;

    float4 acc = make_float4(0.f, 0.f, 0.f, 0.f);
    for (int b0 = 0; b0 < cnt; b0 += 32) {
        int m = cnt - b0;
        int idx = (b0 + lane < cnt) ? g_adjb[base + b0 + lane] : 0;
        if (m >= 32) {
            #pragma unroll
            for (int j = 0; j < 32; j++) {
                int nb = __shfl_sync(0xffffffffu, idx, j);
                float4 v = *(const float4*)&x[(size_t)nb * IN_DIM + lane * 4];
                acc.x += v.x; acc.y += v.y; acc.z += v.z; acc.w += v.w;
            }
        } else {
            for (int j = 0; j < m; j++) {
                int nb = __shfl_sync(0xffffffffu, idx, j);
                float4 v = *(const float4*)&x[(size_t)nb * IN_DIM + lane * 4];
                acc.x += v.x; acc.y += v.y; acc.z += v.z; acc.w += v.w;
            }
        }
    }

    float inv = 1.0f / fmaxf((float)cnt, 1.0f);
    float vv[4] = {acc.x * inv, acc.y * inv, acc.z * inv, acc.w * inv};
    int col = ((seg < n) ? 128 : 256) + lane * 4;
    split_store((size_t)node * K_DIM + col, vv);

    if (seg < n) {   // also convert this node's x row (cols 0..127)
        float4 v = *(const float4*)&x[(size_t)node * IN_DIM + lane * 4];
        float xv[4] = {v.x, v.y, v.z, v.w};
        split_store((size_t)node * K_DIM + lane * 4, xv);
    }
}

// ---------------------------------------------------------------------------
// K4: pipelined fp16 asymmetric-split GEMM. 128x128 tiles, 256 threads
// (8 warps, 4x2), warp tile 32x64, GBK=32, cp.async.ca, 2-stage, 2 CTAs/SM.
// 2 mmas per fragment pair: Ah@Bh + Al@Bh.
// ---------------------------------------------------------------------------
#define GBM 128
#define GBN 128
#define GBK 32
#define A_STRIDE 40      // 32 + 8 pad (fp16)
#define B_STRIDE 136     // 128 + 8 pad (fp16)

#define AH_OFF(st) ((st) * GBM * A_STRIDE)
#define AL_OFF(st) (2 * GBM * A_STRIDE + (st) * GBM * A_STRIDE)
#define BH_OFF(st) (4 * GBM * A_STRIDE + (st) * GBK * B_STRIDE)
#define SMEM_H_TOTAL (4 * GBM * A_STRIDE + 2 * GBK * B_STRIDE)   // 29184 halfs = 58368 B

__device__ __forceinline__ uint32_t smem_u32(const void* p)
{
    return (uint32_t)__cvta_generic_to_shared(p);
}

__device__ __forceinline__ void cp16(uint32_t saddr, const void* g)
{
    asm volatile("cp.async.ca.shared.global [%0], [%1], 16;" :: "r"(saddr), "l"(g));
}

__device__ __forceinline__ void ldsm_x4(uint32_t& r0, uint32_t& r1,
                                        uint32_t& r2, uint32_t& r3, uint32_t addr)
{
    asm volatile("ldmatrix.sync.aligned.m8n8.x4.shared.b16 {%0,%1,%2,%3}, [%4];"
                 : "=r"(r0), "=r"(r1), "=r"(r2), "=r"(r3) : "r"(addr));
}

__device__ __forceinline__ void ldsm_x4_t(uint32_t& r0, uint32_t& r1,
                                          uint32_t& r2, uint32_t& r3, uint32_t addr)
{
    asm volatile("ldmatrix.sync.aligned.m8n8.x4.trans.shared.b16 {%0,%1,%2,%3}, [%4];"
                 : "=r"(r0), "=r"(r1), "=r"(r2), "=r"(r3) : "r"(addr));
}

__device__ __forceinline__ void mma_f16(float c[4], const uint32_t a[4],
                                        const uint32_t b[2])
{
    asm volatile(
        "mma.sync.aligned.m16n8k16.row.col.f32.f16.f16.f32 "
        "{%0,%1,%2,%3}, {%4,%5,%6,%7}, {%8,%9}, {%0,%1,%2,%3};"
        : "+f"(c[0]), "+f"(c[1]), "+f"(c[2]), "+f"(c[3])
        : "r"(a[0]), "r"(a[1]), "r"(a[2]), "r"(a[3]), "r"(b[0]), "r"(b[1]));
}

__global__ __launch_bounds__(256, 2)
void gemm_kernel(const float* __restrict__ bias, float* __restrict__ out, int M)
{
    extern __shared__ __half smem[];
    const uint32_t sbase = smem_u32(smem);

    const int tid  = threadIdx.x;
    const int warp = tid >> 5;
    const int lane = tid & 31;
    const int wm = (warp >> 1) * 32;
    const int wn = (warp & 1) * 64;

    const int rowBase = blockIdx.y * GBM;
    const int colBase = blockIdx.x * GBN;

    float acc[2][8][4];
    #pragma unroll
    for (int i = 0; i < 2; i++)
        #pragma unroll
        for (int j = 0; j < 8; j++)
            #pragma unroll
            for (int c = 0; c < 4; c++) acc[i][j][c] = 0.f;

    auto load_stage = [&](int st, int k0) {
        #pragma unroll
        for (int it = 0; it < 2; it++) {
            int c = tid + it * 256;          // 0..511
            {   // A: 128 rows x 4 chunks of 16B (hi + lo)
                int r = c >> 2, o = (c & 3) * 8;
                size_t gofs = (size_t)(rowBase + r) * K_DIM + k0 + o;
                cp16(sbase + (AH_OFF(st) + r * A_STRIDE + o) * 2, &g_Ahi[gofs]);
                cp16(sbase + (AL_OFF(st) + r * A_STRIDE + o) * 2, &g_Alo[gofs]);
            }
            {   // B: 32 rows x 16 chunks of 16B (single)
                int r = c >> 4, o = (c & 15) * 8;
                size_t gofs = (size_t)(k0 + r) * OUT_DIM + colBase + o;
                cp16(sbase + (BH_OFF(st) + r * B_STRIDE + o) * 2, &g_Bh[gofs]);
            }
        }
        asm volatile("cp.async.commit_group;");
    };

    const int a_row  = lane & 15;
    const int a_koff = (lane >> 4) * 8;
    const int b_k    = lane & 15;
    const int b_noff = (lane >> 4) * 8;

    load_stage(0, 0);

    const int NITER = K_DIM / GBK;           // 12
    for (int itr = 0; itr < NITER; itr++) {
        if (itr + 1 < NITER) {
            load_stage((itr + 1) & 1, (itr + 1) * GBK);
            asm volatile("cp.async.wait_group 1;");
        } else {
            asm volatile("cp.async.wait_group 0;");
        }
        __syncthreads();

        const int st = itr & 1;
        const __half* Ah = smem + AH_OFF(st);
        const __half* Al = smem + AL_OFF(st);
        const __half* Bh = smem + BH_OFF(st);

        #pragma unroll
        for (int kk = 0; kk < GBK; kk += 16) {
            uint32_t ah[2][4], al[2][4];
            #pragma unroll
            for (int mi = 0; mi < 2; mi++) {
                int row = wm + mi * 16 + a_row;
                ldsm_x4(ah[mi][0], ah[mi][1], ah[mi][2], ah[mi][3],
                        smem_u32(Ah + row * A_STRIDE + kk + a_koff));
                ldsm_x4(al[mi][0], al[mi][1], al[mi][2], al[mi][3],
                        smem_u32(Al + row * A_STRIDE + kk + a_koff));
            }
            uint32_t bh[8][2];
            #pragma unroll
            for (int nj = 0; nj < 4; nj++) {
                uint32_t r0, r1, r2, r3;
                ldsm_x4_t(r0, r1, r2, r3,
                          smem_u32(Bh + (kk + b_k) * B_STRIDE + wn + nj * 16 + b_noff));
                bh[nj*2][0] = r0; bh[nj*2][1] = r1;
                bh[nj*2+1][0] = r2; bh[nj*2+1][1] = r3;
            }
            #pragma unroll
            for (int mi = 0; mi < 2; mi++)
                #pragma unroll
                for (int nj = 0; nj < 8; nj++) {
                    mma_f16(acc[mi][nj], ah[mi], bh[nj]);
                    mma_f16(acc[mi][nj], al[mi], bh[nj]);
                }
        }
        __syncthreads();
    }

    // epilogue
    const int g = lane >> 2;
    const int t = lane & 3;
    #pragma unroll
    for (int mi = 0; mi < 2; mi++) {
        int r0 = rowBase + wm + mi * 16 + g;
        int r1 = r0 + 8;
        #pragma unroll
        for (int nj = 0; nj < 8; nj++) {
            int c = colBase + wn + nj * 8 + t * 2;
            float2 bv = *(const float2*)&bias[c];
            if (r0 < M) {
                float2 o;
                o.x = fmaxf(acc[mi][nj][0] + bv.x, 0.f);
                o.y = fmaxf(acc[mi][nj][1] + bv.y, 0.f);
                *(float2*)&out[(size_t)r0 * OUT_DIM + c] = o;
            }
            if (r1 < M) {
                float2 o;
                o.x = fmaxf(acc[mi][nj][2] + bv.x, 0.f);
                o.y = fmaxf(acc[mi][nj][3] + bv.y, 0.f);
                *(float2*)&out[(size_t)r1 * OUT_DIM + c] = o;
            }
        }
    }
}

// ---------------------------------------------------------------------------
// launch — 4 kernels on the default stream: setup, fill, gather, gemm
// ---------------------------------------------------------------------------
extern "C" void kernel_launch(void* const* d_in, const int* in_sizes, int n_in,
                              void* d_out, int out_size)
{
    const float* x = (const float*)d_in[0];
    const int n = in_sizes[0] / IN_DIM;
    float* out = (float*)d_out;

    const float* W;
    const float* b;
    const void* src_buf;
    const void* dst_buf;
    int E;

    if (n_in >= 5) {
        E = in_sizes[1];
        src_buf = d_in[1];
        dst_buf = d_in[2];
        W = (const float*)d_in[3];
        b = (const float*)d_in[4];
    } else {
        E = in_sizes[1] / 2;
        src_buf = d_in[1];
        dst_buf = nullptr;
        W = (const float*)d_in[2];
        b = (const float*)d_in[3];
    }

    setup_kernel<<<512, 256>>>((const long long*)d_in[1], W, n, E);
    fill_kernel<<<(E + 255) / 256, 256>>>(src_buf, dst_buf, n, E);
    {
        long long threads = (long long)(2 * n) * 32;
        gather_kernel<<<(int)((threads + 255) / 256), 256>>>(x, n);
    }
    {
        static const int smem_bytes = SMEM_H_TOTAL * 2;   // 58368
        cudaFuncSetAttribute(gemm_kernel,
                             cudaFuncAttributeMaxDynamicSharedMemorySize, smem_bytes);
        dim3 grid(OUT_DIM / GBN, M_PAD / GBM);
        gemm_kernel<<<grid, 256, smem_bytes>>>(b, out, n);
    }
}